// round 10
// baseline (speedup 1.0000x reference)
#include <cuda_runtime.h>
#include <cuda_fp16.h>

#define N_NODES 100000
#define N_EDGES 3200000
#define NB_SCAN 391            // ceil(N_NODES/256)

// ---------------- scratch ----------------
__device__ int      g_is64;
__device__ int      g_count[N_NODES];     // re-zeroed inside k_scanfused each run
__device__ int      g_ticket;             // re-zeroed by k_scatter for next replay
__device__ unsigned g_state[NB_SCAN];     // look-back {val<<2|status}; re-zeroed by k_scatter
__device__ int      g_off[N_NODES + 1];
__device__ int      g_cursor[N_NODES];
__device__ float    g_dinv[N_NODES];
__device__ int      g_src[N_EDGES];       // CSR src only (4B/edge)
__device__ __half   g_x16[N_NODES * 32];  // x padded 22->32 fp16; scaled by dinv in k_scatter
__device__ float    g_aggX[N_NODES * 32]; // aggregated raw features (fp32)
__device__ __half   g_h16[N_NODES * 64];  // layer-2 agg input, PRE-SCALED by dinv[node]

// ---------------- fused init: pad x, detect dtype, count degrees ----------------
__global__ void k_initcount(const float* __restrict__ x, const int* __restrict__ ei32) {
    __shared__ int s_is64;
    int t = threadIdx.x;
    if (t < 32) {
        int any = ei32[2 * t + 1] | ei32[2 * (t + 32) + 1];
        for (int off = 16; off; off >>= 1) any |= __shfl_xor_sync(0xffffffffu, any, off);
        if (t == 0) {
            s_is64 = (any == 0) ? 1 : 0;
            if (blockIdx.x == 0) g_is64 = s_is64;
        }
    }
    int i = blockIdx.x * blockDim.x + t;
    if (i < N_NODES * 32) {
        int n = i >> 5, c = i & 31;
        g_x16[i] = __float2half_rn((c < 22) ? x[n * 22 + c] : 0.f);
    }
    __syncthreads();
    int is64 = s_is64;
    int d = is64 ? ei32[2 * (N_EDGES + i)] : ei32[N_EDGES + i];
    if ((unsigned)d < N_NODES) atomicAdd(&g_count[d], 1);
}

// ---------------- single-kernel decoupled look-back scan ----------------
__global__ void k_scanfused() {
    __shared__ int smbid;
    __shared__ int wsum[8];
    __shared__ int sprefix;
    int t = threadIdx.x;
    if (t == 0) smbid = atomicAdd(&g_ticket, 1);
    __syncthreads();
    int bid = smbid;
    int i = bid * 256 + t;
    int c = (i < N_NODES) ? g_count[i] : 0;
    if (i < N_NODES) {
        g_dinv[i] = rsqrtf((float)c + 1.0f);   // +1 self-loop
        g_count[i] = 0;                        // ready for next replay
    }
    int lane = t & 31, wid = t >> 5;
    int s = c;
#pragma unroll
    for (int off = 1; off < 32; off <<= 1) {
        int u = __shfl_up_sync(0xffffffffu, s, off);
        if (lane >= off) s += u;
    }
    if (lane == 31) wsum[wid] = s;
    __syncthreads();
    if (wid == 0) {
        int ws = (lane < 8) ? wsum[lane] : 0;
#pragma unroll
        for (int off = 1; off < 8; off <<= 1) {
            int u = __shfl_up_sync(0xffffffffu, ws, off);
            if (lane >= off) ws += u;
        }
        if (lane < 8) wsum[lane] = ws;
    }
    __syncthreads();
    int incl = s + (wid ? wsum[wid - 1] : 0);
    int total = wsum[7];
    if (t == 0) {
        atomicExch(&g_state[bid], ((unsigned)total << 2) | 1u);
        int prefix = 0;
        for (int j = bid - 1; j >= 0;) {
            unsigned st = atomicAdd(&g_state[j], 0u);
            unsigned tag = st & 3u;
            if (tag == 2u) { prefix += (int)(st >> 2); break; }
            if (tag == 1u) { prefix += (int)(st >> 2); j--; }
        }
        atomicExch(&g_state[bid], ((unsigned)(prefix + total) << 2) | 2u);
        sprefix = prefix;
    }
    __syncthreads();
    int prefix = sprefix;
    if (i < N_NODES) {
        int excl = prefix + incl - c;
        g_off[i] = excl;
        g_cursor[i] = excl;
    }
    if (bid == NB_SCAN - 1 && t == 255) g_off[N_NODES] = prefix + incl;
}

// scatter + scale x16 by dinv + reset look-back state for next replay
__global__ void k_scatter(const int* __restrict__ ei32) {
    int e = blockIdx.x * blockDim.x + threadIdx.x;
    if (e < NB_SCAN) g_state[e] = 0u;
    if (e == NB_SCAN) g_ticket = 0;
    {
        float dn = g_dinv[e >> 5];
        g_x16[e] = __float2half_rn(__half2float(g_x16[e]) * dn);
    }
    int is64 = g_is64;
    int s = is64 ? ei32[2 * e] : ei32[e];
    int d = is64 ? ei32[2 * (N_EDGES + e)] : ei32[N_EDGES + e];
    if ((unsigned)d < N_NODES && (unsigned)s < N_NODES) {
        int pos = atomicAdd(&g_cursor[d], 1);
        g_src[pos] = s;
    }
}

// aggX[d] = dinv[d]*(xs[d] + sum_e xs[src_e]); warp = 2 half-warps, each
// processes one edge per step via __half2 loads; pair-HADD2 then float2 accum.
__global__ void k_agg1() {
    int w = (blockIdx.x * blockDim.x + threadIdx.x) >> 5;
    int lane = threadIdx.x & 31;
    if (w >= N_NODES) return;
    float di = g_dinv[w];
    const __half2* __restrict__ x2 = (const __half2*)g_x16;  // 16 half2 per node
    int half = lane >> 4, fl = lane & 15;
    float2 a0 = make_float2(0.f, 0.f), a1 = make_float2(0.f, 0.f);
    if (half == 0) a0 = __half22float2(x2[w * 16 + fl]);      // self term once
    int lo = g_off[w], hi = g_off[w + 1];
    int base = lo;
    int nfull = (hi - lo) & ~31;
    for (; base < lo + nfull; base += 32) {
        int sv = g_src[base + lane];
#pragma unroll
        for (int k = 0; k < 32; k += 8) {
            // this half-warp handles edges k+half, k+2+half, k+4+half, k+6+half
            int s0 = __shfl_sync(0xffffffffu, sv, k + half);
            int s1 = __shfl_sync(0xffffffffu, sv, k + 2 + half);
            int s2 = __shfl_sync(0xffffffffu, sv, k + 4 + half);
            int s3 = __shfl_sync(0xffffffffu, sv, k + 6 + half);
            __half2 p0 = __hadd2(x2[s0 * 16 + fl], x2[s1 * 16 + fl]);
            __half2 p1 = __hadd2(x2[s2 * 16 + fl], x2[s3 * 16 + fl]);
            float2 v0 = __half22float2(p0);
            float2 v1 = __half22float2(p1);
            a0.x += v0.x; a0.y += v0.y;
            a1.x += v1.x; a1.y += v1.y;
        }
    }
    int rem = hi - base;
    if (rem > 0) {
        int idx = base + lane;
        int sv = (idx < hi) ? g_src[idx] : 0;
        for (int j = 0; j < rem; j += 2) {
            int jj = j + half;
            int sj = __shfl_sync(0xffffffffu, sv, (jj < rem) ? jj : 0);
            if (jj < rem) {
                float2 v = __half22float2(x2[sj * 16 + fl]);
                a0.x += v.x; a0.y += v.y;
            }
        }
    }
    float sx = a0.x + a1.x, sy = a0.y + a1.y;
    sx += __shfl_xor_sync(0xffffffffu, sx, 16);
    sy += __shfl_xor_sync(0xffffffffu, sy, 16);
    if (half == 0) {
        float2 o; o.x = di * sx; o.y = di * sy;
        ((float2*)g_aggX)[w * 16 + fl] = o;
    }
}

// h16 = fp16( dinv[node] * (relu(aggX@W1+b1)@W2) ); 32 nodes / 256-thread block
__global__ void k_xform12(const float* __restrict__ W1, const float* __restrict__ b1,
                          const float* __restrict__ W2) {
    __shared__ float W1s[22 * 64];
    __shared__ float W2s[64 * 64];
    __shared__ float h1s[4 * 64];
    __shared__ float as[4 * 22];
    int t = threadIdx.x;
    for (int i = t; i < 22 * 64; i += 256) W1s[i] = W1[i];
    for (int i = t; i < 64 * 64; i += 256) W2s[i] = W2[i];
    int r = t >> 6, j = t & 63;
    float b1j = b1[j];
#pragma unroll
    for (int p = 0; p < 8; p++) {
        int nb = blockIdx.x * 32 + p * 4;
        __syncthreads();
        for (int i = t; i < 4 * 22; i += 256) {
            int n = nb + i / 22;
            as[i] = (n < N_NODES) ? g_aggX[n * 32 + (i % 22)] : 0.f;
        }
        __syncthreads();
        float a = 0.f;
#pragma unroll
        for (int k = 0; k < 22; k++) a += as[r * 22 + k] * W1s[k * 64 + j];
        h1s[r * 64 + j] = fmaxf(a + b1j, 0.f);
        __syncthreads();
        float acc = 0.f;
#pragma unroll
        for (int k = 0; k < 64; k++) acc += h1s[r * 64 + k] * W2s[k * 64 + j];
        int node = nb + r;
        if (node < N_NODES)
            g_h16[node * 64 + j] = __float2half_rn(acc * g_dinv[node]);
    }
}

// layer-2 agg fused with head; pair-HADD2 then float2 accumulation
__global__ void k_agg2f(const float* __restrict__ b2, const float* __restrict__ Wf,
                        const float* __restrict__ bf, float* __restrict__ out) {
    int w = (blockIdx.x * blockDim.x + threadIdx.x) >> 5;
    int lane = threadIdx.x & 31;
    if (w >= N_NODES) return;
    float di = g_dinv[w];
    const __half2* __restrict__ h2 = (const __half2*)g_h16;  // 32 half2 per node
    float2 acc0 = __half22float2(h2[w * 32 + lane]);          // self term
    float2 acc1 = make_float2(0.f, 0.f);
    int lo = g_off[w], hi = g_off[w + 1];
    int base = lo;
    int nfull = (hi - lo) & ~31;
    for (; base < lo + nfull; base += 32) {
        int sv = g_src[base + lane];
#pragma unroll
        for (int j = 0; j < 32; j += 4) {
            int s0 = __shfl_sync(0xffffffffu, sv, j);
            int s1 = __shfl_sync(0xffffffffu, sv, j + 1);
            int s2 = __shfl_sync(0xffffffffu, sv, j + 2);
            int s3 = __shfl_sync(0xffffffffu, sv, j + 3);
            __half2 p0 = __hadd2(h2[s0 * 32 + lane], h2[s1 * 32 + lane]);
            __half2 p1 = __hadd2(h2[s2 * 32 + lane], h2[s3 * 32 + lane]);
            float2 v0 = __half22float2(p0);
            float2 v1 = __half22float2(p1);
            acc0.x += v0.x; acc0.y += v0.y;
            acc1.x += v1.x; acc1.y += v1.y;
        }
    }
    int rem = hi - base;
    if (rem > 0) {
        int idx = base + lane;
        int sv = (idx < hi) ? g_src[idx] : 0;
        for (int j = 0; j < rem; j++) {
            int sj = __shfl_sync(0xffffffffu, sv, j);
            float2 hv = __half22float2(h2[sj * 32 + lane]);
            acc0.x += hv.x; acc0.y += hv.y;
        }
    }
    float ax = di * (acc0.x + acc1.x);
    float ay = di * (acc0.y + acc1.y);
    float r0 = fmaxf(ax + b2[2 * lane], 0.f) * Wf[2 * lane];
    float r1 = fmaxf(ay + b2[2 * lane + 1], 0.f) * Wf[2 * lane + 1];
    float s = r0 + r1;
#pragma unroll
    for (int off = 16; off; off >>= 1) s += __shfl_xor_sync(0xffffffffu, s, off);
    if (lane == 0) out[w] = s + bf[0];
}

// ---------------- launch ----------------
extern "C" void kernel_launch(void* const* d_in, const int* in_sizes, int n_in,
                              void* d_out, int out_size) {
    const float* x   = (const float*)d_in[0];
    const int*   ei  = (const int*)d_in[1];
    const float* W1  = (const float*)d_in[2];
    const float* b1  = (const float*)d_in[3];
    const float* W2  = (const float*)d_in[4];
    const float* b2  = (const float*)d_in[5];
    const float* Wf  = (const float*)d_in[6];
    const float* bf  = (const float*)d_in[7];
    float* out = (float*)d_out;

    const int TB = 256;
    int gE = (N_EDGES + TB - 1) / TB;        // 12500 == N_NODES*32/256
    int gW = (N_NODES * 32 + TB - 1) / TB;
    int gT = (N_NODES + 31) / 32;

    k_initcount<<<gE, TB>>>(x, ei);
    k_scanfused<<<NB_SCAN, 256>>>();
    k_scatter<<<gE, TB>>>(ei);
    k_agg1<<<gW, TB>>>();
    k_xform12<<<gT, TB>>>(W1, b1, W2);
    k_agg2f<<<gW, TB>>>(b2, Wf, bf, out);
}

// round 11
// speedup vs baseline: 1.0360x; 1.0360x over previous
#include <cuda_runtime.h>
#include <cuda_fp16.h>

#define N_NODES 100000
#define N_EDGES 3200000
#define NB_SCAN 391            // ceil(N_NODES/256)

// ---------------- scratch ----------------
__device__ int      g_is64;
__device__ int      g_count[N_NODES];     // re-zeroed inside k_scanfused each run
__device__ int      g_ticket;             // re-zeroed by k_scatter for next replay
__device__ unsigned g_state[NB_SCAN];     // look-back {val<<2|status}; re-zeroed by k_scatter
__device__ int      g_off[N_NODES + 1];
__device__ int      g_cursor[N_NODES];
__device__ float    g_dinv[N_NODES];
__device__ int      g_src[N_EDGES];       // CSR src only (4B/edge)
__device__ __half   g_x16[N_NODES * 32];  // x padded 22->32 fp16, scaled by dinv (64B/node)
__device__ float    g_aggX[N_NODES * 32]; // aggregated raw features (fp32)
__device__ __half   g_h16[N_NODES * 64];  // layer-2 agg input, PRE-SCALED by dinv (128B/node)

// ---------------- fused init: pad x, detect dtype, count degrees ----------------
__global__ void k_initcount(const float* __restrict__ x, const int* __restrict__ ei32) {
    __shared__ int s_is64;
    int t = threadIdx.x;
    if (t < 32) {
        int any = ei32[2 * t + 1] | ei32[2 * (t + 32) + 1];
        for (int off = 16; off; off >>= 1) any |= __shfl_xor_sync(0xffffffffu, any, off);
        if (t == 0) {
            s_is64 = (any == 0) ? 1 : 0;
            if (blockIdx.x == 0) g_is64 = s_is64;
        }
    }
    int i = blockIdx.x * blockDim.x + t;
    if (i < N_NODES * 32) {
        int n = i >> 5, c = i & 31;
        g_x16[i] = __float2half_rn((c < 22) ? x[n * 22 + c] : 0.f);
    }
    __syncthreads();
    int is64 = s_is64;
    int d = is64 ? ei32[2 * (N_EDGES + i)] : ei32[N_EDGES + i];
    if ((unsigned)d < N_NODES) atomicAdd(&g_count[d], 1);
}

// ---------------- single-kernel decoupled look-back scan ----------------
__global__ void k_scanfused() {
    __shared__ int smbid;
    __shared__ int wsum[8];
    __shared__ int sprefix;
    int t = threadIdx.x;
    if (t == 0) smbid = atomicAdd(&g_ticket, 1);
    __syncthreads();
    int bid = smbid;
    int i = bid * 256 + t;
    int c = (i < N_NODES) ? g_count[i] : 0;
    if (i < N_NODES) {
        g_dinv[i] = rsqrtf((float)c + 1.0f);   // +1 self-loop
        g_count[i] = 0;
    }
    int lane = t & 31, wid = t >> 5;
    int s = c;
#pragma unroll
    for (int off = 1; off < 32; off <<= 1) {
        int u = __shfl_up_sync(0xffffffffu, s, off);
        if (lane >= off) s += u;
    }
    if (lane == 31) wsum[wid] = s;
    __syncthreads();
    if (wid == 0) {
        int ws = (lane < 8) ? wsum[lane] : 0;
#pragma unroll
        for (int off = 1; off < 8; off <<= 1) {
            int u = __shfl_up_sync(0xffffffffu, ws, off);
            if (lane >= off) ws += u;
        }
        if (lane < 8) wsum[lane] = ws;
    }
    __syncthreads();
    int incl = s + (wid ? wsum[wid - 1] : 0);
    int total = wsum[7];
    if (t == 0) {
        atomicExch(&g_state[bid], ((unsigned)total << 2) | 1u);
        int prefix = 0;
        for (int j = bid - 1; j >= 0;) {
            unsigned st = atomicAdd(&g_state[j], 0u);
            unsigned tag = st & 3u;
            if (tag == 2u) { prefix += (int)(st >> 2); break; }
            if (tag == 1u) { prefix += (int)(st >> 2); j--; }
        }
        atomicExch(&g_state[bid], ((unsigned)(prefix + total) << 2) | 2u);
        sprefix = prefix;
    }
    __syncthreads();
    int prefix = sprefix;
    if (i < N_NODES) {
        int excl = prefix + incl - c;
        g_off[i] = excl;
        g_cursor[i] = excl;
    }
    if (bid == NB_SCAN - 1 && t == 255) g_off[N_NODES] = prefix + incl;
}

// scatter + scale x16 by dinv + reset look-back state for next replay
__global__ void k_scatter(const int* __restrict__ ei32) {
    int e = blockIdx.x * blockDim.x + threadIdx.x;
    if (e < NB_SCAN) g_state[e] = 0u;
    if (e == NB_SCAN) g_ticket = 0;
    {
        float dn = g_dinv[e >> 5];
        g_x16[e] = __float2half_rn(__half2float(g_x16[e]) * dn);
    }
    int is64 = g_is64;
    int s = is64 ? ei32[2 * e] : ei32[e];
    int d = is64 ? ei32[2 * (N_EDGES + e)] : ei32[N_EDGES + e];
    if ((unsigned)d < N_NODES && (unsigned)s < N_NODES) {
        int pos = atomicAdd(&g_cursor[d], 1);
        g_src[pos] = s;
    }
}

// aggX[d] = dinv[d]*(xs[d] + sum_e xs[src_e]).
// Warp per node; 8 lanes per edge (uint2 = 4 fp16 features), 4 edges per LDG.
__global__ void k_agg1() {
    int w = (blockIdx.x * blockDim.x + threadIdx.x) >> 5;
    int lane = threadIdx.x & 31;
    if (w >= N_NODES) return;
    float di = g_dinv[w];
    const uint2* __restrict__ x4 = (const uint2*)g_x16;   // 8 uint2 per node
    int grp = lane >> 3, fl = lane & 7;
    float a0 = 0.f, a1 = 0.f, a2 = 0.f, a3 = 0.f;
    if (grp == 0) {   // self term once
        uint2 v = x4[w * 8 + fl];
        float2 f0 = __half22float2(*(__half2*)&v.x);
        float2 f1 = __half22float2(*(__half2*)&v.y);
        a0 = f0.x; a1 = f0.y; a2 = f1.x; a3 = f1.y;
    }
    int lo = g_off[w], hi = g_off[w + 1];
    int base = lo;
    int nfull = (hi - lo) & ~31;
    for (; base < lo + nfull; base += 32) {
        int sv = g_src[base + lane];
#pragma unroll
        for (int r = 0; r < 8; r++) {           // 8 rounds x 4 edges
            int sj = __shfl_sync(0xffffffffu, sv, r * 4 + grp);
            uint2 v = x4[sj * 8 + fl];
            float2 f0 = __half22float2(*(__half2*)&v.x);
            float2 f1 = __half22float2(*(__half2*)&v.y);
            a0 += f0.x; a1 += f0.y; a2 += f1.x; a3 += f1.y;
        }
    }
    int rem = hi - base;
    if (rem > 0) {
        int idx = base + lane;
        int sv = (idx < hi) ? g_src[idx] : 0;
        for (int j = 0; j < rem; j += 4) {
            int jj = j + grp;
            int sj = __shfl_sync(0xffffffffu, sv, (jj < rem) ? jj : 0);
            if (jj < rem) {
                uint2 v = x4[sj * 8 + fl];
                float2 f0 = __half22float2(*(__half2*)&v.x);
                float2 f1 = __half22float2(*(__half2*)&v.y);
                a0 += f0.x; a1 += f0.y; a2 += f1.x; a3 += f1.y;
            }
        }
    }
    // reduce across the 4 groups (lane bits 3,4)
#pragma unroll
    for (int off = 8; off <= 16; off <<= 1) {
        a0 += __shfl_xor_sync(0xffffffffu, a0, off);
        a1 += __shfl_xor_sync(0xffffffffu, a1, off);
        a2 += __shfl_xor_sync(0xffffffffu, a2, off);
        a3 += __shfl_xor_sync(0xffffffffu, a3, off);
    }
    if (grp == 0) {
        float4 o = make_float4(di * a0, di * a1, di * a2, di * a3);
        ((float4*)g_aggX)[w * 8 + fl] = o;   // features fl*4 .. fl*4+3
    }
}

// h16 = fp16( dinv[node] * (relu(aggX@W1+b1)@W2) ); 32 nodes / 256-thread block
__global__ void k_xform12(const float* __restrict__ W1, const float* __restrict__ b1,
                          const float* __restrict__ W2) {
    __shared__ float W1s[22 * 64];
    __shared__ float W2s[64 * 64];
    __shared__ float h1s[4 * 64];
    __shared__ float as[4 * 22];
    int t = threadIdx.x;
    for (int i = t; i < 22 * 64; i += 256) W1s[i] = W1[i];
    for (int i = t; i < 64 * 64; i += 256) W2s[i] = W2[i];
    int r = t >> 6, j = t & 63;
    float b1j = b1[j];
#pragma unroll
    for (int p = 0; p < 8; p++) {
        int nb = blockIdx.x * 32 + p * 4;
        __syncthreads();
        for (int i = t; i < 4 * 22; i += 256) {
            int n = nb + i / 22;
            as[i] = (n < N_NODES) ? g_aggX[n * 32 + (i % 22)] : 0.f;
        }
        __syncthreads();
        float a = 0.f;
#pragma unroll
        for (int k = 0; k < 22; k++) a += as[r * 22 + k] * W1s[k * 64 + j];
        h1s[r * 64 + j] = fmaxf(a + b1j, 0.f);
        __syncthreads();
        float acc = 0.f;
#pragma unroll
        for (int k = 0; k < 64; k++) acc += h1s[r * 64 + k] * W2s[k * 64 + j];
        int node = nb + r;
        if (node < N_NODES)
            g_h16[node * 64 + j] = __float2half_rn(acc * g_dinv[node]);
    }
}

// layer-2 agg + head. Warp per node; 8 lanes per edge (uint4 = 8 fp16 features).
__global__ void k_agg2f(const float* __restrict__ b2, const float* __restrict__ Wf,
                        const float* __restrict__ bf, float* __restrict__ out) {
    int w = (blockIdx.x * blockDim.x + threadIdx.x) >> 5;
    int lane = threadIdx.x & 31;
    if (w >= N_NODES) return;
    float di = g_dinv[w];
    const uint4* __restrict__ h4 = (const uint4*)g_h16;   // 8 uint4 per node
    int grp = lane >> 3, fl = lane & 7;
    float a[8] = {0.f, 0.f, 0.f, 0.f, 0.f, 0.f, 0.f, 0.f};
    if (grp == 0) {   // self term
        uint4 v = h4[w * 8 + fl];
        float2 f0 = __half22float2(*(__half2*)&v.x);
        float2 f1 = __half22float2(*(__half2*)&v.y);
        float2 f2 = __half22float2(*(__half2*)&v.z);
        float2 f3 = __half22float2(*(__half2*)&v.w);
        a[0] = f0.x; a[1] = f0.y; a[2] = f1.x; a[3] = f1.y;
        a[4] = f2.x; a[5] = f2.y; a[6] = f3.x; a[7] = f3.y;
    }
    int lo = g_off[w], hi = g_off[w + 1];
    int base = lo;
    int nfull = (hi - lo) & ~31;
    for (; base < lo + nfull; base += 32) {
        int sv = g_src[base + lane];
#pragma unroll
        for (int r = 0; r < 8; r++) {
            int sj = __shfl_sync(0xffffffffu, sv, r * 4 + grp);
            uint4 v = h4[sj * 8 + fl];
            float2 f0 = __half22float2(*(__half2*)&v.x);
            float2 f1 = __half22float2(*(__half2*)&v.y);
            float2 f2 = __half22float2(*(__half2*)&v.z);
            float2 f3 = __half22float2(*(__half2*)&v.w);
            a[0] += f0.x; a[1] += f0.y; a[2] += f1.x; a[3] += f1.y;
            a[4] += f2.x; a[5] += f2.y; a[6] += f3.x; a[7] += f3.y;
        }
    }
    int rem = hi - base;
    if (rem > 0) {
        int idx = base + lane;
        int sv = (idx < hi) ? g_src[idx] : 0;
        for (int j = 0; j < rem; j += 4) {
            int jj = j + grp;
            int sj = __shfl_sync(0xffffffffu, sv, (jj < rem) ? jj : 0);
            if (jj < rem) {
                uint4 v = h4[sj * 8 + fl];
                float2 f0 = __half22float2(*(__half2*)&v.x);
                float2 f1 = __half22float2(*(__half2*)&v.y);
                float2 f2 = __half22float2(*(__half2*)&v.z);
                float2 f3 = __half22float2(*(__half2*)&v.w);
                a[0] += f0.x; a[1] += f0.y; a[2] += f1.x; a[3] += f1.y;
                a[4] += f2.x; a[5] += f2.y; a[6] += f3.x; a[7] += f3.y;
            }
        }
    }
    // reduce across the 4 groups -> every lane holds full sums for its fl slot
#pragma unroll
    for (int off = 8; off <= 16; off <<= 1) {
#pragma unroll
        for (int k = 0; k < 8; k++) a[k] += __shfl_xor_sync(0xffffffffu, a[k], off);
    }
    // head: lane's features are fl*8 + k
    float s = 0.f;
#pragma unroll
    for (int k = 0; k < 8; k++) {
        int f = fl * 8 + k;
        s += fmaxf(di * a[k] + b2[f], 0.f) * Wf[f];
    }
    // sum across fl lanes (bits 0..2); every group computes the same value
    s += __shfl_xor_sync(0xffffffffu, s, 1);
    s += __shfl_xor_sync(0xffffffffu, s, 2);
    s += __shfl_xor_sync(0xffffffffu, s, 4);
    if (lane == 0) out[w] = s + bf[0];
}

// ---------------- launch ----------------
extern "C" void kernel_launch(void* const* d_in, const int* in_sizes, int n_in,
                              void* d_out, int out_size) {
    const float* x   = (const float*)d_in[0];
    const int*   ei  = (const int*)d_in[1];
    const float* W1  = (const float*)d_in[2];
    const float* b1  = (const float*)d_in[3];
    const float* W2  = (const float*)d_in[4];
    const float* b2  = (const float*)d_in[5];
    const float* Wf  = (const float*)d_in[6];
    const float* bf  = (const float*)d_in[7];
    float* out = (float*)d_out;

    const int TB = 256;
    int gE = (N_EDGES + TB - 1) / TB;        // 12500 == N_NODES*32/256
    int gW = (N_NODES * 32 + TB - 1) / TB;
    int gT = (N_NODES + 31) / 32;

    k_initcount<<<gE, TB>>>(x, ei);
    k_scanfused<<<NB_SCAN, 256>>>();
    k_scatter<<<gE, TB>>>(ei);
    k_agg1<<<gW, TB>>>();
    k_xform12<<<gT, TB>>>(W1, b1, W2);
    k_agg2f<<<gW, TB>>>(b2, Wf, bf, out);
}